// round 3
// baseline (speedup 1.0000x reference)
#include <cuda_runtime.h>

#define NMAX 20002
#define EMAX 120000
#define TMAX 2097152
#define DHIST 16384
#define NBM 8192 /* TMAX/256 */

__device__ int g_srcHist[NMAX], g_tgtHist[NMAX];
__device__ int g_srcBase[NMAX], g_tgtBase[NMAX];
__device__ int g_curA[NMAX], g_curB[NMAX], g_curC[NMAX];
__device__ int g_eScat[EMAX], g_ePerm[EMAX];
__device__ int g_srcS[EMAX], g_tgtS[EMAX];
__device__ int g_oScat[EMAX], g_order[EMAX];
__device__ int g_prod[NMAX], g_prefixG[NMAX];
__device__ int g_tri0[TMAX], g_tri1[TMAX], g_tri2[TMAX];   // raw tri; reused as kept tri
__device__ int g_triS0[TMAX], g_triS1[TMAX], g_triS2[TMAX]; // sorted tri
__device__ int g_tScat[TMAX], g_tPerm[TMAX];
__device__ int g_histTri[NMAX], g_triBase[NMAX];
__device__ int g_deg[NMAX];
__device__ int g_histD[DHIST + 2], g_cumD[DHIST + 2];
__device__ int g_maxNode, g_dstar, g_r;
__device__ int g_tieEx[NMAX], g_keep[NMAX];
__device__ int g_blockSums[NBM + 2], g_blockOff[NBM + 2];
__device__ int g_srcPresent[NMAX], g_present[NMAX];
__device__ int g_srcRank[NMAX], g_rank[NMAX];
__device__ int g_segHead[NMAX];
__device__ float g_Wt[3 * 64 * 64]; // Wt[k*4096 + i*64 + o] = W[o][i][k]

// ---- block exclusive scan of one int per thread; returns excl, *tot = total
__device__ __forceinline__ int blockScanEx(int v, int* tot) {
    __shared__ int s_w[32];
    __shared__ int s_tot;
    int lane = threadIdx.x & 31, wid = threadIdx.x >> 5, nw = blockDim.x >> 5;
    int inc = v;
#pragma unroll
    for (int o = 1; o < 32; o <<= 1) {
        int u = __shfl_up_sync(0xffffffffu, inc, o);
        if (lane >= o) inc += u;
    }
    if (lane == 31) s_w[wid] = inc;
    __syncthreads();
    if (wid == 0) {
        int sv = (lane < nw) ? s_w[lane] : 0;
        int si = sv;
#pragma unroll
        for (int o = 1; o < 32; o <<= 1) {
            int u = __shfl_up_sync(0xffffffffu, si, o);
            if (lane >= o) si += u;
        }
        s_w[lane] = si - sv;
        if (lane == 31) s_tot = si;
    }
    __syncthreads();
    int ex = inc - v + s_w[wid];
    *tot = s_tot;
    __syncthreads();
    return ex;
}

// single-block (1024 thr) exclusive scan; out[n] = total
__device__ void sbScan(const int* in, int* out, int n) {
    int carry = 0;
    for (int base = 0; base < n; base += 8192) {
        int i0 = base + threadIdx.x * 8;
        int v[8], pre[8], loc = 0;
#pragma unroll
        for (int j = 0; j < 8; j++) {
            int i = i0 + j;
            v[j] = (i < n) ? in[i] : 0;
            pre[j] = loc; loc += v[j];
        }
        int tot, ex = blockScanEx(loc, &tot);
#pragma unroll
        for (int j = 0; j < 8; j++) {
            int i = i0 + j;
            if (i < n) out[i] = carry + ex + pre[j];
        }
        carry += tot;
    }
    if (threadIdx.x == 0) out[n] = carry;
}

__global__ void kInit(int N) {
    int i = blockIdx.x * blockDim.x + threadIdx.x;
    if (i < N) {
        g_srcHist[i] = 0; g_tgtHist[i] = 0;
        g_curA[i] = 0; g_curB[i] = 0; g_curC[i] = 0;
        g_histTri[i] = 0; g_deg[i] = 0;
        g_srcPresent[i] = 0; g_present[i] = 0;
    }
    if (i < DHIST) g_histD[i] = 0;
    if (i == 0) g_maxNode = -1;
}

__global__ void kWt(const float* __restrict__ W) {
    int t = blockIdx.x * blockDim.x + threadIdx.x;
    if (t >= 3 * 64 * 64) return;
    int o = t & 63, i = (t >> 6) & 63, k = t >> 12;
    g_Wt[t] = W[o * 192 + i * 3 + k];
}

__global__ void kEdgeHist(const int* __restrict__ ei, int E) {
    int e = blockIdx.x * blockDim.x + threadIdx.x;
    if (e >= E) return;
    atomicAdd(&g_srcHist[ei[e]], 1);
    atomicAdd(&g_tgtHist[ei[E + e]], 1);
}

__global__ void __launch_bounds__(1024) kScanBases(int N) {
    sbScan(g_srcHist, g_srcBase, N);
    sbScan(g_tgtHist, g_tgtBase, N);
}

__global__ void kScatterSrc(const int* __restrict__ ei, int E) {
    int e = blockIdx.x * blockDim.x + threadIdx.x;
    if (e >= E) return;
    int v = ei[e];
    g_eScat[g_srcBase[v] + atomicAdd(&g_curA[v], 1)] = e;
}

__global__ void kSortSrc(const int* __restrict__ ei, int E, int N) {
    int w = (blockIdx.x * blockDim.x + threadIdx.x) >> 5;
    int lane = threadIdx.x & 31;
    if (w >= N) return;
    int lo = g_srcBase[w], s = g_srcBase[w + 1] - lo;
    for (int i = lane; i < s; i += 32) {
        int val = g_eScat[lo + i], r = 0;
        for (int j = 0; j < s; j++) r += (g_eScat[lo + j] < val);
        g_ePerm[lo + r] = val;
    }
    __syncwarp();
    for (int i = lane; i < s; i += 32) {
        int e = g_ePerm[lo + i];
        g_srcS[lo + i] = w;
        g_tgtS[lo + i] = ei[E + e];
    }
}

__global__ void kScatterTgt(int E) {
    int j = blockIdx.x * blockDim.x + threadIdx.x;
    if (j >= E) return;
    int w = g_tgtS[j];
    g_oScat[g_tgtBase[w] + atomicAdd(&g_curB[w], 1)] = j;
}

__global__ void kSortOrder(int N) {
    int w = (blockIdx.x * blockDim.x + threadIdx.x) >> 5;
    int lane = threadIdx.x & 31;
    if (w >= N) return;
    int lo = g_tgtBase[w], s = g_tgtBase[w + 1] - lo;
    for (int i = lane; i < s; i += 32) {
        int val = g_oScat[lo + i], r = 0;
        for (int j = 0; j < s; j++) r += (g_oScat[lo + j] < val);
        g_order[lo + r] = val;
    }
}

__global__ void kProd(int N) {
    int v = blockIdx.x * blockDim.x + threadIdx.x;
    if (v >= N) return;
    g_prod[v] = (g_srcBase[v + 1] - g_srcBase[v]) * (g_tgtBase[v + 1] - g_tgtBase[v]);
}

__global__ void __launch_bounds__(1024) kScanProd(int N) { sbScan(g_prod, g_prefixG, N); }

__global__ void kGen(int E) {
    int e = blockIdx.x * blockDim.x + threadIdx.x;
    if (e >= E) return;
    int v = g_srcS[e];
    int lb = g_tgtBase[v];
    int din = g_tgtBase[v + 1] - lb;
    if (din <= 0) return;
    int t0 = g_prefixG[v] + (e - g_srcBase[v]) * din;
    int w = g_tgtS[e];
    int mx = v > w ? v : w;
    for (int off = 0; off < din; off++) {
        int t = t0 + off;
        if (t >= TMAX) break;
        int a = g_srcS[g_order[lb + off]];
        g_tri0[t] = a; g_tri1[t] = v; g_tri2[t] = w;
        atomicAdd(&g_histTri[a], 1);
        atomicAdd(&g_deg[a], 1);
        if (a > mx) mx = a;
    }
    atomicAdd(&g_deg[v], din);
    atomicAdd(&g_deg[w], din);
    atomicMax(&g_maxNode, mx);
}

__global__ void __launch_bounds__(1024) kScanTriBase(int N) { sbScan(g_histTri, g_triBase, N); }

__global__ void kScatterTri(int N) {
    int t = blockIdx.x * blockDim.x + threadIdx.x;
    int T = g_prefixG[N]; if (T > TMAX) T = TMAX;
    if (t >= T) return;
    int a = g_tri0[t];
    g_tScat[g_triBase[a] + atomicAdd(&g_curC[a], 1)] = t;
}

__global__ void kSortTri(int N) {
    int w = (blockIdx.x * blockDim.x + threadIdx.x) >> 5;
    int lane = threadIdx.x & 31;
    if (w >= N) return;
    int lo = g_triBase[w], s = g_triBase[w + 1] - lo;
    for (int i = lane; i < s; i += 32) {
        int val = g_tScat[lo + i], r = 0;
        for (int j = 0; j < s; j++) r += (g_tScat[lo + j] < val);
        g_tPerm[lo + r] = val;
    }
    __syncwarp();
    for (int i = lane; i < s; i += 32) {
        int t = g_tPerm[lo + i];
        g_triS0[lo + i] = g_tri0[t];
        g_triS1[lo + i] = g_tri1[t];
        g_triS2[lo + i] = g_tri2[t];
    }
}

__global__ void kHistD(int N) {
    int i = blockIdx.x * blockDim.x + threadIdx.x;
    if (i >= N) return;
    int L = g_maxNode + 1;
    if (i < L) {
        int d = g_deg[i];
        if (d > DHIST - 1) d = DHIST - 1;
        atomicAdd(&g_histD[d], 1);
    }
}

__global__ void __launch_bounds__(1024) kScanHistD() { sbScan(g_histD, g_cumD, DHIST); }

__global__ void kFindDstar() {
    int d = blockIdx.x * blockDim.x + threadIdx.x;
    if (d >= DHIST) return;
    int half = (g_maxNode + 1) >> 1;
    if (g_cumD[d] <= half && half < g_cumD[d + 1]) {
        g_dstar = d;
        g_r = half - g_cumD[d];
    }
}

__global__ void kInd(int N) {
    int i = blockIdx.x * blockDim.x + threadIdx.x;
    if (i >= N) return;
    int L = g_maxNode + 1;
    g_prod[i] = (i < L && g_deg[i] == g_dstar) ? 1 : 0;
}

__global__ void __launch_bounds__(1024) kScanInd(int N) { sbScan(g_prod, g_tieEx, N); }

__global__ void kKeep(int N) {
    int i = blockIdx.x * blockDim.x + threadIdx.x;
    if (i >= N) return;
    int L = g_maxNode + 1, kp = 1;
    if (i < L) {
        int d = g_deg[i];
        if (d < g_dstar) kp = 0;
        else if (d == g_dstar && g_tieEx[i] < g_r) kp = 0;
    }
    g_keep[i] = kp;
}

__global__ void __launch_bounds__(256) kMaskA(int N) {
    int T = g_prefixG[N]; if (T > TMAX) T = TMAX;
    int t = blockIdx.x * 256 + threadIdx.x;
    int m = 0;
    if (t < T)
        m = g_keep[g_triS0[t]] & g_keep[g_triS1[t]] & g_keep[g_triS2[t]];
    int tot;
    blockScanEx(m, &tot);
    if (threadIdx.x == 0) g_blockSums[blockIdx.x] = tot;
}

__global__ void __launch_bounds__(1024) kScanBlk() { sbScan(g_blockSums, g_blockOff, NBM); }

__global__ void __launch_bounds__(256) kMaskC(int N) {
    int T = g_prefixG[N]; if (T > TMAX) T = TMAX;
    int t = blockIdx.x * 256 + threadIdx.x;
    int m = 0, a = 0, b = 0, c = 0;
    if (t < T) {
        a = g_triS0[t]; b = g_triS1[t]; c = g_triS2[t];
        m = g_keep[a] & g_keep[b] & g_keep[c];
    }
    int tot, ex = blockScanEx(m, &tot);
    if (m) {
        int p = g_blockOff[blockIdx.x] + ex;
        g_tri0[p] = a; g_tri1[p] = b; g_tri2[p] = c;
        g_srcPresent[a] = 1;
        g_present[a] = 1; g_present[b] = 1; g_present[c] = 1;
    }
}

__global__ void __launch_bounds__(1024) kScanPresent(int N) {
    sbScan(g_srcPresent, g_srcRank, N);
    sbScan(g_present, g_rank, N);
    if (threadIdx.x == 0) g_segHead[g_srcRank[N]] = g_blockOff[NBM]; // segHead[U] = P
}

__global__ void kSegHead() {
    int p = blockIdx.x * blockDim.x + threadIdx.x;
    int P = g_blockOff[NBM];
    if (p >= P) return;
    int a = g_tri0[p];
    if (p == 0 || g_tri0[p - 1] != a) g_segHead[g_srcRank[a]] = p;
}

__global__ void __launch_bounds__(256) kCompute(const float* __restrict__ x,
                                                const float* __restrict__ bvec,
                                                float* __restrict__ out, int N) {
    __shared__ float sv[8][192];
    int u = (blockIdx.x * blockDim.x + threadIdx.x) >> 5;
    int lane = threadIdx.x & 31, w = (threadIdx.x >> 5);
    int U = g_srcRank[N];
    if (u >= U) return;
    int h0 = g_segHead[u], h1 = g_segHead[u + 1];
    int a = g_tri0[h0];
    float sB0 = 0.f, sB1 = 0.f, sC0 = 0.f, sC1 = 0.f;
    for (int p = h0; p < h1; p++) {
        const float* xb = x + g_tri1[p] * 64;
        const float* xc = x + g_tri2[p] * 64;
        sB0 += xb[lane]; sB1 += xb[lane + 32];
        sC0 += xc[lane]; sC1 += xc[lane + 32];
    }
    float inv = 1.0f / (float)(h1 - h0);
    sv[w][lane] = x[a * 64 + lane];
    sv[w][lane + 32] = x[a * 64 + lane + 32];
    sv[w][64 + lane] = sB0 * inv;
    sv[w][64 + lane + 32] = sB1 * inv;
    sv[w][128 + lane] = sC0 * inv;
    sv[w][128 + lane + 32] = sC1 * inv;
    __syncwarp();
    float acc0 = bvec[lane], acc1 = bvec[lane + 32];
#pragma unroll 8
    for (int i = 0; i < 64; i++) {
        float v0 = sv[w][i], v1 = sv[w][64 + i], v2 = sv[w][128 + i];
        int base = i * 64 + lane;
        acc0 += g_Wt[base] * v0 + g_Wt[4096 + base] * v1 + g_Wt[8192 + base] * v2;
        acc1 += g_Wt[base + 32] * v0 + g_Wt[4096 + base + 32] * v1 + g_Wt[8192 + base + 32] * v2;
    }
    out[u * 64 + lane] = acc0;
    out[u * 64 + lane + 32] = acc1;
}

__global__ void kNewEi(float* __restrict__ out, int N) {
    int p = blockIdx.x * blockDim.x + threadIdx.x;
    int P = g_blockOff[NBM];
    if (p >= P) return;
    int U = g_srcRank[N];
    int base = 64 * U;
    out[base + p]         = (float)g_rank[g_tri0[p]];
    out[base + P + p]     = (float)g_rank[g_tri1[p]];
    out[base + 2 * P + p] = (float)g_rank[g_tri2[p]];
}

extern "C" void kernel_launch(void* const* d_in, const int* in_sizes, int n_in,
                              void* d_out, int out_size) {
    const float* x = (const float*)d_in[0];
    const int* ei = (const int*)d_in[1];
    const float* W = (const float*)d_in[2];
    const float* b = (const float*)d_in[3];
    float* out = (float*)d_out;
    int N = in_sizes[0] / 64;
    int E = in_sizes[1] / 2;
    int nb = (N + 255) / 256, eb = (E + 255) / 256;
    int wb = (N * 32 + 255) / 256;           // warp-per-node grids
    int tb = (TMAX + 255) / 256;             // grids covering TMAX with early exit

    kInit<<<(DHIST > N ? DHIST + 255 : N + 255) / 256, 256>>>(N);
    kWt<<<48, 256>>>(W);
    kEdgeHist<<<eb, 256>>>(ei, E);
    kScanBases<<<1, 1024>>>(N);
    kScatterSrc<<<eb, 256>>>(ei, E);
    kSortSrc<<<wb, 256>>>(ei, E, N);
    kScatterTgt<<<eb, 256>>>(E);
    kSortOrder<<<wb, 256>>>(N);
    kProd<<<nb, 256>>>(N);
    kScanProd<<<1, 1024>>>(N);
    kGen<<<eb, 256>>>(E);
    kScanTriBase<<<1, 1024>>>(N);
    kScatterTri<<<tb, 256>>>(N);
    kSortTri<<<wb, 256>>>(N);
    kHistD<<<nb, 256>>>(N);
    kScanHistD<<<1, 1024>>>();
    kFindDstar<<<DHIST / 256, 256>>>();
    kInd<<<nb, 256>>>(N);
    kScanInd<<<1, 1024>>>(N);
    kKeep<<<nb, 256>>>(N);
    kMaskA<<<NBM, 256>>>(N);
    kScanBlk<<<1, 1024>>>();
    kMaskC<<<NBM, 256>>>(N);
    kScanPresent<<<1, 1024>>>(N);
    kSegHead<<<tb, 256>>>();
    kCompute<<<(N / 2 * 32 + 255) / 256 + 1, 256>>>(x, b, out, N);
    kNewEi<<<tb, 256>>>(out, N);
}

// round 4
// speedup vs baseline: 1.0151x; 1.0151x over previous
#include <cuda_runtime.h>

#define NS 20480          /* node arrays padded to 1024*5*4 for int4 scans */
#define EMAX 120000
#define TMAX 2097152
#define DHIST 16384
#define NTILE 2048        /* TMAX / 1024 lookback tiles */

__device__ __align__(16) int g_srcHist[NS + 8], g_tgtHist[NS + 8];
__device__ __align__(16) int g_srcBase[NS + 8], g_tgtBase[NS + 8];
__device__ int g_curA[NS + 8], g_curB[NS + 8], g_curC[NS + 8];
__device__ int g_eScat[EMAX], g_ePerm[EMAX];
__device__ int g_srcS[EMAX], g_tgtS[EMAX];
__device__ int g_oScat[EMAX], g_order[EMAX];
__device__ __align__(16) int g_prod[NS + 8], g_prefixG[NS + 8];
__device__ int g_tri0[TMAX], g_tri1[TMAX], g_tri2[TMAX];        // raw tri; reused as kept tri
__device__ __align__(16) int g_triS0[TMAX], g_triS1[TMAX], g_triS2[TMAX];
__device__ int g_tScat[TMAX], g_tPerm[TMAX];
__device__ __align__(16) int g_histTri[NS + 8];
__device__ int g_triBase[NS + 8];
__device__ int g_deg[NS + 8];
__device__ __align__(16) int g_histD[DHIST + 8];
__device__ int g_cumD[DHIST + 8];
__device__ int g_maxNode, g_P;
__device__ __align__(16) int g_tieEx[NS + 8];
__device__ int g_keep[NS + 8];
__device__ __align__(16) int g_srcPresent[NS + 8], g_present[NS + 8];
__device__ int g_srcRank[NS + 8], g_rank[NS + 8];
__device__ int g_segHead[NS + 8];
__device__ float g_Wt[3 * 64 * 64];   // Wt[k*4096 + i*64 + o] = W[o][i][k]
__device__ volatile unsigned long long g_tileState[NTILE + 2];

// ---- block exclusive scan; returns exclusive prefix, *tot = block total
__device__ __forceinline__ int blockScanEx(int v, int* tot) {
    __shared__ int s_w[32];
    __shared__ int s_tot;
    int lane = threadIdx.x & 31, wid = threadIdx.x >> 5, nw = blockDim.x >> 5;
    int inc = v;
#pragma unroll
    for (int o = 1; o < 32; o <<= 1) {
        int u = __shfl_up_sync(0xffffffffu, inc, o);
        if (lane >= o) inc += u;
    }
    if (lane == 31) s_w[wid] = inc;
    __syncthreads();
    if (wid == 0) {
        int sv = (lane < nw) ? s_w[lane] : 0;
        int si = sv;
#pragma unroll
        for (int o = 1; o < 32; o <<= 1) {
            int u = __shfl_up_sync(0xffffffffu, si, o);
            if (lane >= o) si += u;
        }
        s_w[lane] = si - sv;
        if (lane == 31) s_tot = si;
    }
    __syncthreads();
    int ex = inc - v + s_w[wid];
    *tot = s_tot;
    __syncthreads();
    return ex;
}

// single-pass vectorized single-block scan: n <= 1024*VPT4*4, input zero-padded
template <int VPT4>
__device__ void sbScanFast(const int* in, int* out, int n) {
    int v[VPT4 * 4];
    const int4* in4 = (const int4*)in;
#pragma unroll
    for (int j = 0; j < VPT4; j++) {
        int4 q = in4[threadIdx.x * VPT4 + j];
        v[4 * j] = q.x; v[4 * j + 1] = q.y; v[4 * j + 2] = q.z; v[4 * j + 3] = q.w;
    }
    int loc = 0;
#pragma unroll
    for (int j = 0; j < VPT4 * 4; j++) { int t = v[j]; v[j] = loc; loc += t; }
    int tot, ex = blockScanEx(loc, &tot);
    int base = threadIdx.x * VPT4 * 4;
#pragma unroll
    for (int j = 0; j < VPT4 * 4; j++) {
        int i = base + j;
        if (i < n) out[i] = ex + v[j];
    }
    if (threadIdx.x == 0) out[n] = tot;
}

__global__ void kInit(const float* __restrict__ W, int N) {
    int i = blockIdx.x * blockDim.x + threadIdx.x;
    if (i < NS) {
        g_srcHist[i] = 0; g_tgtHist[i] = 0; g_histTri[i] = 0;
        g_deg[i] = 0; g_srcPresent[i] = 0; g_present[i] = 0;
        g_curA[i] = 0; g_curB[i] = 0; g_curC[i] = 0;
    }
    if (i < DHIST) g_histD[i] = 0;
    if (i <= NTILE) g_tileState[i] = 0ull;
    if (i < 12288) {
        int o = i & 63, ii = (i >> 6) & 63, k = i >> 12;
        g_Wt[i] = W[o * 192 + ii * 3 + k];
    }
    if (i == 0) g_maxNode = -1;
}

__global__ void kEdgeHist(const int* __restrict__ ei, int E) {
    int e = blockIdx.x * blockDim.x + threadIdx.x;
    if (e >= E) return;
    atomicAdd(&g_srcHist[ei[e]], 1);
    atomicAdd(&g_tgtHist[ei[E + e]], 1);
}

__global__ void __launch_bounds__(1024) kScanBasesProd(int N) {
    for (int i = threadIdx.x; i < NS; i += 1024)
        g_prod[i] = (i < N) ? g_srcHist[i] * g_tgtHist[i] : 0;
    __syncthreads();
    sbScanFast<5>(g_srcHist, g_srcBase, N);
    sbScanFast<5>(g_tgtHist, g_tgtBase, N);
    sbScanFast<5>(g_prod, g_prefixG, N);
}

__global__ void kScatterSrc(const int* __restrict__ ei, int E) {
    int e = blockIdx.x * blockDim.x + threadIdx.x;
    if (e >= E) return;
    int v = ei[e];
    g_eScat[g_srcBase[v] + atomicAdd(&g_curA[v], 1)] = e;
}

__global__ void kSortSrc(const int* __restrict__ ei, int E, int N) {
    int w = (blockIdx.x * blockDim.x + threadIdx.x) >> 5;
    int lane = threadIdx.x & 31;
    if (w >= N) return;
    int lo = g_srcBase[w], s = g_srcBase[w + 1] - lo;
    for (int i = lane; i < s; i += 32) {
        int val = g_eScat[lo + i], r = 0;
        for (int j = 0; j < s; j++) r += (g_eScat[lo + j] < val);
        g_ePerm[lo + r] = val;
    }
    __syncwarp();
    for (int i = lane; i < s; i += 32) {
        int e = g_ePerm[lo + i];
        g_srcS[lo + i] = w;
        g_tgtS[lo + i] = ei[E + e];
    }
}

__global__ void kScatterTgt(int E) {
    int j = blockIdx.x * blockDim.x + threadIdx.x;
    if (j >= E) return;
    int w = g_tgtS[j];
    g_oScat[g_tgtBase[w] + atomicAdd(&g_curB[w], 1)] = j;
}

__global__ void kSortOrder(int N) {
    int w = (blockIdx.x * blockDim.x + threadIdx.x) >> 5;
    int lane = threadIdx.x & 31;
    if (w >= N) return;
    int lo = g_tgtBase[w], s = g_tgtBase[w + 1] - lo;
    for (int i = lane; i < s; i += 32) {
        int val = g_oScat[lo + i], r = 0;
        for (int j = 0; j < s; j++) r += (g_oScat[lo + j] < val);
        g_order[lo + r] = val;
    }
}

__global__ void kGen(int E) {
    int e = blockIdx.x * blockDim.x + threadIdx.x;
    if (e >= E) return;
    int v = g_srcS[e];
    int lb = g_tgtBase[v];
    int din = g_tgtBase[v + 1] - lb;
    if (din <= 0) return;
    int t0 = g_prefixG[v] + (e - g_srcBase[v]) * din;
    int w = g_tgtS[e];
    int mx = v > w ? v : w;
    for (int off = 0; off < din; off++) {
        int t = t0 + off;
        if (t >= TMAX) break;
        int a = g_srcS[g_order[lb + off]];
        g_tri0[t] = a; g_tri1[t] = v; g_tri2[t] = w;
        atomicAdd(&g_histTri[a], 1);
        atomicAdd(&g_deg[a], 1);
        if (a > mx) mx = a;
    }
    atomicAdd(&g_deg[v], din);
    atomicAdd(&g_deg[w], din);
    atomicMax(&g_maxNode, mx);
}

__global__ void __launch_bounds__(1024) kScanTriBase(int N) { sbScanFast<5>(g_histTri, g_triBase, N); }

__global__ void kScatterTri(int N) {
    int t = blockIdx.x * blockDim.x + threadIdx.x;
    int T = g_prefixG[N]; if (T > TMAX) T = TMAX;
    if (t >= T) return;
    int a = g_tri0[t];
    g_tScat[g_triBase[a] + atomicAdd(&g_curC[a], 1)] = t;
}

__global__ void kSortTri(int N) {
    int w = (blockIdx.x * blockDim.x + threadIdx.x) >> 5;
    int lane = threadIdx.x & 31;
    if (w >= N) return;
    int lo = g_triBase[w], s = g_triBase[w + 1] - lo;
    for (int i = lane; i < s; i += 32) {
        int val = g_tScat[lo + i], r = 0;
        for (int j = 0; j < s; j++) r += (g_tScat[lo + j] < val);
        g_tPerm[lo + r] = val;
    }
    __syncwarp();
    for (int i = lane; i < s; i += 32) {
        int t = g_tPerm[lo + i];
        g_triS0[lo + i] = g_tri0[t];
        g_triS1[lo + i] = g_tri1[t];
        g_triS2[lo + i] = g_tri2[t];
    }
}

__global__ void kHistD(int N) {
    int i = blockIdx.x * blockDim.x + threadIdx.x;
    if (i >= N) return;
    if (i < g_maxNode + 1) {
        int d = g_deg[i];
        if (d > DHIST - 1) d = DHIST - 1;
        atomicAdd(&g_histD[d], 1);
    }
}

// scan histD -> cumD, find (dstar, r), build indicator, scan it, compute keep.
__global__ void __launch_bounds__(1024) kSelect(int N) {
    __shared__ int s_dstar, s_r;
    sbScanFast<4>(g_histD, g_cumD, DHIST);
    __syncthreads();
    int L = g_maxNode + 1;
    int half = L >> 1;
    for (int d = threadIdx.x; d < DHIST; d += 1024)
        if (g_cumD[d] <= half && half < g_cumD[d + 1]) { s_dstar = d; s_r = half - g_cumD[d]; }
    __syncthreads();
    int dstar = s_dstar, r = s_r;
    for (int i = threadIdx.x; i < NS; i += 1024)
        g_prod[i] = (i < L && g_deg[i] == dstar) ? 1 : 0;
    __syncthreads();
    sbScanFast<5>(g_prod, g_tieEx, N);
    __syncthreads();
    for (int i = threadIdx.x; i < N; i += 1024) {
        int kp = 1;
        if (i < L) {
            int d = g_deg[i];
            if (d < dstar) kp = 0;
            else if (d == dstar && g_tieEx[i] < r) kp = 0;
        }
        g_keep[i] = kp;
    }
}

// single-pass mask + order-preserving compaction via decoupled lookback
__global__ void __launch_bounds__(256) kMaskScatter(int N) {
    int T = g_prefixG[N]; if (T > TMAX) T = TMAX;
    int tile = blockIdx.x;
    int t0 = tile * 1024 + threadIdx.x * 4;
    int idx4 = t0 >> 2;
    int4 A = ((const int4*)g_triS0)[idx4];
    int4 B = ((const int4*)g_triS1)[idx4];
    int4 C = ((const int4*)g_triS2)[idx4];
    int av[4] = {A.x, A.y, A.z, A.w};
    int bv[4] = {B.x, B.y, B.z, B.w};
    int cv[4] = {C.x, C.y, C.z, C.w};
    int m[4], s = 0;
#pragma unroll
    for (int j = 0; j < 4; j++) {
        m[j] = 0;
        if (t0 + j < T) m[j] = g_keep[av[j]] & g_keep[bv[j]] & g_keep[cv[j]];
        s += m[j];
    }
    int tot, ex = blockScanEx(s, &tot);
    __shared__ int s_exTile;
    if (threadIdx.x == 0) {
        if (tile == 0) {
            g_tileState[0] = (2ull << 32) | (unsigned)tot;
            s_exTile = 0;
            if (NTILE == 1) g_P = tot;
        } else {
            g_tileState[tile] = (1ull << 32) | (unsigned)tot;
            int exT = 0;
            int p = tile - 1;
            while (true) {
                unsigned long long st = g_tileState[p];
                unsigned f = (unsigned)(st >> 32);
                if (f == 0) continue;
                exT += (int)(st & 0xffffffffu);
                if (f == 2) break;
                p--;
            }
            s_exTile = exT;
            g_tileState[tile] = (2ull << 32) | (unsigned)(exT + tot);
            if (tile == NTILE - 1) g_P = exT + tot;
        }
    }
    __syncthreads();
    int o = s_exTile + ex;
#pragma unroll
    for (int j = 0; j < 4; j++) {
        if (m[j]) {
            g_tri0[o] = av[j]; g_tri1[o] = bv[j]; g_tri2[o] = cv[j];
            g_srcPresent[av[j]] = 1;
            g_present[av[j]] = 1; g_present[bv[j]] = 1; g_present[cv[j]] = 1;
            o++;
        }
    }
}

__global__ void __launch_bounds__(1024) kScanPresent(int N) {
    sbScanFast<5>(g_srcPresent, g_srcRank, N);
    sbScanFast<5>(g_present, g_rank, N);
    if (threadIdx.x == 0) g_segHead[g_srcRank[N]] = g_P;   // segHead[U] = P
}

// writes new_ei into the output tail AND marks segment heads for kCompute
__global__ void kNewEiSeg(float* __restrict__ out, int N) {
    int p = blockIdx.x * blockDim.x + threadIdx.x;
    int P = g_P;
    if (p >= P) return;
    int a = g_tri0[p];
    int U = g_srcRank[N];
    int base = 64 * U;
    out[base + p]         = (float)g_rank[a];
    out[base + P + p]     = (float)g_rank[g_tri1[p]];
    out[base + 2 * P + p] = (float)g_rank[g_tri2[p]];
    if (p == 0 || g_tri0[p - 1] != a) g_segHead[g_srcRank[a]] = p;
}

__global__ void __launch_bounds__(256) kCompute(const float* __restrict__ x,
                                                const float* __restrict__ bvec,
                                                float* __restrict__ out, int N) {
    __shared__ float sv[8][192];
    int u = (blockIdx.x * blockDim.x + threadIdx.x) >> 5;
    int lane = threadIdx.x & 31, w = (threadIdx.x >> 5);
    int U = g_srcRank[N];
    if (u >= U) return;
    int h0 = g_segHead[u], h1 = g_segHead[u + 1];
    int a = g_tri0[h0];
    float sB0 = 0.f, sB1 = 0.f, sC0 = 0.f, sC1 = 0.f;
    for (int p = h0; p < h1; p++) {
        const float* xb = x + g_tri1[p] * 64;
        const float* xc = x + g_tri2[p] * 64;
        sB0 += xb[lane]; sB1 += xb[lane + 32];
        sC0 += xc[lane]; sC1 += xc[lane + 32];
    }
    float inv = 1.0f / (float)(h1 - h0);
    sv[w][lane] = x[a * 64 + lane];
    sv[w][lane + 32] = x[a * 64 + lane + 32];
    sv[w][64 + lane] = sB0 * inv;
    sv[w][64 + lane + 32] = sB1 * inv;
    sv[w][128 + lane] = sC0 * inv;
    sv[w][128 + lane + 32] = sC1 * inv;
    __syncwarp();
    float acc0 = bvec[lane], acc1 = bvec[lane + 32];
#pragma unroll 8
    for (int i = 0; i < 64; i++) {
        float v0 = sv[w][i], v1 = sv[w][64 + i], v2 = sv[w][128 + i];
        int base = i * 64 + lane;
        acc0 += g_Wt[base] * v0 + g_Wt[4096 + base] * v1 + g_Wt[8192 + base] * v2;
        acc1 += g_Wt[base + 32] * v0 + g_Wt[4096 + base + 32] * v1 + g_Wt[8192 + base + 32] * v2;
    }
    out[u * 64 + lane] = acc0;
    out[u * 64 + lane + 32] = acc1;
}

extern "C" void kernel_launch(void* const* d_in, const int* in_sizes, int n_in,
                              void* d_out, int out_size) {
    const float* x = (const float*)d_in[0];
    const int* ei = (const int*)d_in[1];
    const float* W = (const float*)d_in[2];
    const float* b = (const float*)d_in[3];
    float* out = (float*)d_out;
    int N = in_sizes[0] / 64;
    int E = in_sizes[1] / 2;
    int nb = (N + 255) / 256, eb = (E + 255) / 256;
    int wb = (N * 32 + 255) / 256;
    int tb = (TMAX + 255) / 256;

    kInit<<<NS / 256, 256>>>(W, N);
    kEdgeHist<<<eb, 256>>>(ei, E);
    kScanBasesProd<<<1, 1024>>>(N);
    kScatterSrc<<<eb, 256>>>(ei, E);
    kSortSrc<<<wb, 256>>>(ei, E, N);
    kScatterTgt<<<eb, 256>>>(E);
    kSortOrder<<<wb, 256>>>(N);
    kGen<<<eb, 256>>>(E);
    kScanTriBase<<<1, 1024>>>(N);
    kScatterTri<<<tb, 256>>>(N);
    kSortTri<<<wb, 256>>>(N);
    kHistD<<<nb, 256>>>(N);
    kSelect<<<1, 1024>>>(N);
    kMaskScatter<<<NTILE, 256>>>(N);
    kScanPresent<<<1, 1024>>>(N);
    kNewEiSeg<<<tb, 256>>>(out, N);
    kCompute<<<(N / 2 * 32 + 255) / 256 + 1, 256>>>(x, b, out, N);
}